// round 2
// baseline (speedup 1.0000x reference)
#include <cuda_runtime.h>
#include <math.h>

// Problem shape (fixed by the reference)
#define BB 64
#define II 2048
#define JJ 16
#define MM 16
#define NN 16
#define JM 256            // J*M
#define NCHUNK 16
#define CHUNK 128         // II / NCHUNK
#define SQ_EPS 1e-8f

// ---------------- scratch (static device globals; no runtime allocation) ----
__device__ float g_hat[(size_t)BB * II * JM];     // 134 MB : inputs_hat [b][i][j*16+m]
__device__ float g_blog[(size_t)BB * II * JJ];    // 8 MB   : routing logits b1
__device__ float g_spart[BB * NCHUNK * JM];       // 1 MB   : partial s sums
__device__ float g_outbuf[2 * BB * JM];           // squashed outputs (slots 0/1)

// ---------------------------------------------------------------------------
// Kernel 1: inputs_hat[b,i,j,m] = sum_n W[i,j,n,m] * x[b,i,n]
// One block per i. W[i] (4096 f32) and x[:,i,:] (1024 f32) staged in SMEM.
// Thread t = j*16+m computes one output column across all 64 b.
// ---------------------------------------------------------------------------
__global__ void __launch_bounds__(256) hat_kernel(const float* __restrict__ x,
                                                  const float* __restrict__ W) {
    __shared__ float Ws[4096];
    __shared__ float xs[BB * NN];
    const int i = blockIdx.x;
    const int t = threadIdx.x;

    // Stage W[i]: 1024 float4, coalesced
    const float4* Wg = (const float4*)(W + (size_t)i * 4096);
    float4* Ws4 = (float4*)Ws;
#pragma unroll
    for (int k = 0; k < 4; k++) Ws4[t + 256 * k] = Wg[t + 256 * k];

    // Stage x[:, i, :]: 256 float4 (4 per batch row)
    {
        const int b = t >> 2, n4 = t & 3;
        ((float4*)xs)[t] = ((const float4*)(x + ((size_t)b * II + i) * NN))[n4];
    }
    __syncthreads();

    const int j = t >> 4, m = t & 15;
    float w[16];
#pragma unroll
    for (int n = 0; n < 16; n++) w[n] = Ws[j * 256 + n * 16 + m];

    float* dst = g_hat + (size_t)i * JM + t;
#pragma unroll 2
    for (int b = 0; b < BB; b++) {
        const float4* xb = (const float4*)(xs + b * 16);
        float4 a0 = xb[0], a1 = xb[1], a2 = xb[2], a3 = xb[3];
        // 4 independent FMA chains for ILP
        float s0 = a0.x * w[0];
        float s1 = a0.y * w[1];
        float s2 = a0.z * w[2];
        float s3 = a0.w * w[3];
        s0 = fmaf(a1.x, w[4], s0);
        s1 = fmaf(a1.y, w[5], s1);
        s2 = fmaf(a1.z, w[6], s2);
        s3 = fmaf(a1.w, w[7], s3);
        s0 = fmaf(a2.x, w[8], s0);
        s1 = fmaf(a2.y, w[9], s1);
        s2 = fmaf(a2.z, w[10], s2);
        s3 = fmaf(a2.w, w[11], s3);
        s0 = fmaf(a3.x, w[12], s0);
        s1 = fmaf(a3.y, w[13], s1);
        s2 = fmaf(a3.z, w[14], s2);
        s3 = fmaf(a3.w, w[15], s3);
        dst[(size_t)b * II * JM] = (s0 + s1) + (s2 + s3);
    }
}

// ---------------------------------------------------------------------------
// Routing pass over hat. One block per (chunk of 128 i's, batch b).
// 256 threads = 16 ii-lanes x 16 j. Each thread handles (i=base+ii+16*tt, j),
// reads its 16-float hat row, computes delta_j (dot with prev outputs),
// softmax over j via 16-lane shfl groups, accumulates c_ij * hat into
// per-thread s accumulator; block-reduces over ii into g_spart.
// MODE: 0 = iteration 0 (uniform c, no logits)
//       1 = iteration 1 (b = delta, write g_blog)
//       2 = iteration 2 (b = g_blog + delta, no write)
// ---------------------------------------------------------------------------
template <int MODE>
__global__ void __launch_bounds__(256) pass_kernel(int prev_slot) {
    const int chunk = blockIdx.x;  // 0..15
    const int b = blockIdx.y;      // 0..63
    const int t = threadIdx.x;
    const int ii = t >> 4, j = t & 15;

    float op[16];
    if (MODE != 0) {
        const float4* o4 =
            (const float4*)(g_outbuf + (size_t)prev_slot * BB * JM + b * JM + j * 16);
        float4 v0 = o4[0], v1 = o4[1], v2 = o4[2], v3 = o4[3];
        op[0] = v0.x; op[1] = v0.y; op[2] = v0.z; op[3] = v0.w;
        op[4] = v1.x; op[5] = v1.y; op[6] = v1.z; op[7] = v1.w;
        op[8] = v2.x; op[9] = v2.y; op[10] = v2.z; op[11] = v2.w;
        op[12] = v3.x; op[13] = v3.y; op[14] = v3.z; op[15] = v3.w;
    }

    float acc[16];
#pragma unroll
    for (int m = 0; m < 16; m++) acc[m] = 0.f;

    const int ibase = chunk * CHUNK;
    for (int tt = 0; tt < CHUNK / 16; tt++) {
        const int i = ibase + tt * 16 + ii;
        const float4* h4 =
            (const float4*)(g_hat + ((size_t)b * II + i) * JM + j * 16);
        float4 h0 = h4[0], h1 = h4[1], h2 = h4[2], h3 = h4[3];

        float cij;
        if (MODE == 0) {
            cij = 0.0625f;  // softmax of zeros over 16
        } else {
            float d0 = op[0] * h0.x;
            float d1 = op[4] * h1.x;
            float d2 = op[8] * h2.x;
            float d3 = op[12] * h3.x;
            d0 = fmaf(op[1], h0.y, d0);
            d1 = fmaf(op[5], h1.y, d1);
            d2 = fmaf(op[9], h2.y, d2);
            d3 = fmaf(op[13], h3.y, d3);
            d0 = fmaf(op[2], h0.z, d0);
            d1 = fmaf(op[6], h1.z, d1);
            d2 = fmaf(op[10], h2.z, d2);
            d3 = fmaf(op[14], h3.z, d3);
            d0 = fmaf(op[3], h0.w, d0);
            d1 = fmaf(op[7], h1.w, d1);
            d2 = fmaf(op[11], h2.w, d2);
            d3 = fmaf(op[15], h3.w, d3);
            float bv = (d0 + d1) + (d2 + d3);
            if (MODE == 2) bv += g_blog[((size_t)b * II + i) * JJ + j];
            // softmax over j: 16-lane groups (xor offsets <16 stay in-group)
            float mx = bv;
#pragma unroll
            for (int o = 8; o >= 1; o >>= 1)
                mx = fmaxf(mx, __shfl_xor_sync(0xffffffffu, mx, o));
            float e = __expf(bv - mx);
            float ssum = e;
#pragma unroll
            for (int o = 8; o >= 1; o >>= 1)
                ssum += __shfl_xor_sync(0xffffffffu, ssum, o);
            cij = __fdividef(e, ssum);
            if (MODE == 1) g_blog[((size_t)b * II + i) * JJ + j] = bv;
        }
        acc[0] = fmaf(cij, h0.x, acc[0]);
        acc[1] = fmaf(cij, h0.y, acc[1]);
        acc[2] = fmaf(cij, h0.z, acc[2]);
        acc[3] = fmaf(cij, h0.w, acc[3]);
        acc[4] = fmaf(cij, h1.x, acc[4]);
        acc[5] = fmaf(cij, h1.y, acc[5]);
        acc[6] = fmaf(cij, h1.z, acc[6]);
        acc[7] = fmaf(cij, h1.w, acc[7]);
        acc[8] = fmaf(cij, h2.x, acc[8]);
        acc[9] = fmaf(cij, h2.y, acc[9]);
        acc[10] = fmaf(cij, h2.z, acc[10]);
        acc[11] = fmaf(cij, h2.w, acc[11]);
        acc[12] = fmaf(cij, h3.x, acc[12]);
        acc[13] = fmaf(cij, h3.y, acc[13]);
        acc[14] = fmaf(cij, h3.z, acc[14]);
        acc[15] = fmaf(cij, h3.w, acc[15]);
    }

    // Deterministic block reduction over ii
    __shared__ float red[16 * JM];
#pragma unroll
    for (int m = 0; m < 16; m += 4) {
        *(float4*)&red[ii * JM + j * 16 + m] =
            make_float4(acc[m], acc[m + 1], acc[m + 2], acc[m + 3]);
    }
    __syncthreads();
    float v = 0.f;
#pragma unroll
    for (int k = 0; k < 16; k++) v += red[k * JM + t];
    g_spart[(b * NCHUNK + chunk) * JM + t] = v;
}

// ---------------------------------------------------------------------------
// Reduce partial s over chunks + squash. One block per b, thread t = j*16+m.
// Writes to g_outbuf[slot] or, for the final iteration, to ext_dst (d_out).
// ---------------------------------------------------------------------------
__global__ void __launch_bounds__(256) squash_kernel(float* ext_dst, int slot) {
    const int b = blockIdx.x;
    const int t = threadIdx.x;
    float s = 0.f;
#pragma unroll
    for (int ch = 0; ch < NCHUNK; ch++) s += g_spart[(b * NCHUNK + ch) * JM + t];
    float n2 = s * s;
#pragma unroll
    for (int o = 8; o >= 1; o >>= 1)
        n2 += __shfl_xor_sync(0xffffffffu, n2, o);
    const float scale = (n2 / (1.f + n2)) * rsqrtf(n2 + SQ_EPS);
    const float outv = scale * s;
    float* dst = ext_dst ? ext_dst : (g_outbuf + (size_t)slot * BB * JM);
    dst[b * JM + t] = outv;
}

// ---------------------------------------------------------------------------
extern "C" void kernel_launch(void* const* d_in, const int* in_sizes, int n_in,
                              void* d_out, int out_size) {
    const float* x = (const float*)d_in[0];  // [B, I, N] : 2097152 elems
    const float* W = (const float*)d_in[1];  // [I, J, N, M] : 8388608 elems
    if (n_in >= 2 && in_sizes[0] > in_sizes[1]) {  // defensive order check
        const float* tmp = x; x = W; W = tmp;
    }
    float* out = (float*)d_out;

    hat_kernel<<<II, 256>>>(x, W);

    dim3 pg(NCHUNK, BB);
    // Iteration 0: uniform coupling
    pass_kernel<0><<<pg, 256>>>(0);
    squash_kernel<<<BB, 256>>>(nullptr, 0);   // -> out0 (slot 0)
    // Iteration 1: b1 = dot(out0, hat); c = softmax(b1)
    pass_kernel<1><<<pg, 256>>>(0);
    squash_kernel<<<BB, 256>>>(nullptr, 1);   // -> out1 (slot 1)
    // Iteration 2: b2 = b1 + dot(out1, hat); c = softmax(b2)
    pass_kernel<2><<<pg, 256>>>(1);
    squash_kernel<<<BB, 256>>>(out, 0);       // final -> d_out
}

// round 3
// speedup vs baseline: 1.0213x; 1.0213x over previous
#include <cuda_runtime.h>
#include <math.h>

// Problem shape (fixed by the reference)
#define BB 64
#define GROUPB 32         // batch tile so hat slice (67 MB) stays L2-resident
#define II 2048
#define JJ 16
#define MM 16
#define NN 16
#define JM 256            // J*M
#define NCHUNK 16
#define CHUNK 128         // II / NCHUNK
#define SQ_EPS 1e-8f

// ---------------- scratch (static device globals; no runtime allocation) ----
__device__ float g_hat[(size_t)BB * II * JM];        // 134 MB (used 67 MB/group)
__device__ float g_blog[(size_t)BB * II * JJ];       // 8 MB routing logits
__device__ float g_spart[2][BB * NCHUNK * JM];       // double-buffered partial s

// ---------------------------------------------------------------------------
// hat for one batch group: inputs_hat[b,i,j,m] = sum_n W[i,j,n,m] * x[b,i,n]
// One block per i; W[i] (16 KB) + x[b0..b0+32, i, :] (2 KB) staged in SMEM.
// ---------------------------------------------------------------------------
__global__ void __launch_bounds__(256) hat_kernel(const float* __restrict__ x,
                                                  const float* __restrict__ W,
                                                  int b0) {
    __shared__ float Ws[4096];
    __shared__ float xs[GROUPB * NN];
    const int i = blockIdx.x;
    const int t = threadIdx.x;

    const float4* Wg = (const float4*)(W + (size_t)i * 4096);
    float4* Ws4 = (float4*)Ws;
#pragma unroll
    for (int k = 0; k < 4; k++) Ws4[t + 256 * k] = Wg[t + 256 * k];

    if (t < GROUPB * 4) {  // 32 b x 4 float4
        const int b = t >> 2, n4 = t & 3;
        ((float4*)xs)[t] =
            ((const float4*)(x + ((size_t)(b0 + b) * II + i) * NN))[n4];
    }
    __syncthreads();

    const int j = t >> 4, m = t & 15;
    float w[16];
#pragma unroll
    for (int n = 0; n < 16; n++) w[n] = Ws[j * 256 + n * 16 + m];

    float* dst = g_hat + (size_t)b0 * II * JM + (size_t)i * JM + t;
#pragma unroll 2
    for (int b = 0; b < GROUPB; b++) {
        const float4* xb = (const float4*)(xs + b * 16);
        float4 a0 = xb[0], a1 = xb[1], a2 = xb[2], a3 = xb[3];
        float s0 = a0.x * w[0];
        float s1 = a0.y * w[1];
        float s2 = a0.z * w[2];
        float s3 = a0.w * w[3];
        s0 = fmaf(a1.x, w[4], s0);
        s1 = fmaf(a1.y, w[5], s1);
        s2 = fmaf(a1.z, w[6], s2);
        s3 = fmaf(a1.w, w[7], s3);
        s0 = fmaf(a2.x, w[8], s0);
        s1 = fmaf(a2.y, w[9], s1);
        s2 = fmaf(a2.z, w[10], s2);
        s3 = fmaf(a2.w, w[11], s3);
        s0 = fmaf(a3.x, w[12], s0);
        s1 = fmaf(a3.y, w[13], s1);
        s2 = fmaf(a3.z, w[14], s2);
        s3 = fmaf(a3.w, w[15], s3);
        dst[(size_t)b * II * JM] = (s0 + s1) + (s2 + s3);
    }
}

// ---------------------------------------------------------------------------
// Routing pass over hat for one batch group. Fuses the squash of the PREVIOUS
// iteration (reduce g_spart[RSLOT] + squash, redundantly per block — cheap
// L2-hit reads) so no separate squash launch is needed between passes.
// MODE: 0 = iter0 (uniform c), 1 = iter1 (b=delta, write blog),
//       2 = iter2 (b=blog+delta)
// spart slots: MODE0 writes 0; MODE1 reads 0, writes 1; MODE2 reads 1, writes 0
// ---------------------------------------------------------------------------
template <int MODE>
__global__ void __launch_bounds__(256) pass_kernel(int b0) {
    const int chunk = blockIdx.x;       // 0..15
    const int b = b0 + blockIdx.y;      // batch index
    const int t = threadIdx.x;
    const int ii = t >> 4, j = t & 15;

    __shared__ float ops[JM];
    __shared__ float red[16 * JM];

    float op[16];
    if (MODE != 0) {
        // Fused squash of previous iteration from g_spart[RSLOT]
        const int RSLOT = (MODE == 1) ? 0 : 1;
        float s = 0.f;
        const float* sp = g_spart[RSLOT] + b * (NCHUNK * JM) + t;
#pragma unroll
        for (int ch = 0; ch < NCHUNK; ch++) s += sp[ch * JM];
        float n2 = s * s;  // reduce over m: low 4 lane bits (t = j*16+m layout)
#pragma unroll
        for (int o = 8; o >= 1; o >>= 1)
            n2 += __shfl_xor_sync(0xffffffffu, n2, o);
        const float scale = (n2 / (1.f + n2)) * rsqrtf(n2 + SQ_EPS);
        ops[t] = scale * s;
        __syncthreads();
        const float4* o4 = (const float4*)(ops + j * 16);
        float4 v0 = o4[0], v1 = o4[1], v2 = o4[2], v3 = o4[3];
        op[0] = v0.x; op[1] = v0.y; op[2] = v0.z; op[3] = v0.w;
        op[4] = v1.x; op[5] = v1.y; op[6] = v1.z; op[7] = v1.w;
        op[8] = v2.x; op[9] = v2.y; op[10] = v2.z; op[11] = v2.w;
        op[12] = v3.x; op[13] = v3.y; op[14] = v3.z; op[15] = v3.w;
    }

    float acc[16];
#pragma unroll
    for (int m = 0; m < 16; m++) acc[m] = 0.f;

    const int ibase = chunk * CHUNK;
    for (int tt = 0; tt < CHUNK / 16; tt++) {
        const int i = ibase + tt * 16 + ii;
        const float4* h4 =
            (const float4*)(g_hat + ((size_t)b * II + i) * JM + j * 16);
        float4 h0 = h4[0], h1 = h4[1], h2 = h4[2], h3 = h4[3];

        float cij;
        if (MODE == 0) {
            cij = 0.0625f;  // softmax of zeros over 16
        } else {
            float d0 = op[0] * h0.x;
            float d1 = op[4] * h1.x;
            float d2 = op[8] * h2.x;
            float d3 = op[12] * h3.x;
            d0 = fmaf(op[1], h0.y, d0);
            d1 = fmaf(op[5], h1.y, d1);
            d2 = fmaf(op[9], h2.y, d2);
            d3 = fmaf(op[13], h3.y, d3);
            d0 = fmaf(op[2], h0.z, d0);
            d1 = fmaf(op[6], h1.z, d1);
            d2 = fmaf(op[10], h2.z, d2);
            d3 = fmaf(op[14], h3.z, d3);
            d0 = fmaf(op[3], h0.w, d0);
            d1 = fmaf(op[7], h1.w, d1);
            d2 = fmaf(op[11], h2.w, d2);
            d3 = fmaf(op[15], h3.w, d3);
            float bv = (d0 + d1) + (d2 + d3);
            if (MODE == 2) bv += g_blog[((size_t)b * II + i) * JJ + j];
            // softmax over j (16-lane groups); |bv| small -> no max pass needed
            float e = __expf(bv);
            float ssum = e;
#pragma unroll
            for (int o = 8; o >= 1; o >>= 1)
                ssum += __shfl_xor_sync(0xffffffffu, ssum, o);
            cij = __fdividef(e, ssum);
            if (MODE == 1) g_blog[((size_t)b * II + i) * JJ + j] = bv;
        }
        acc[0] = fmaf(cij, h0.x, acc[0]);
        acc[1] = fmaf(cij, h0.y, acc[1]);
        acc[2] = fmaf(cij, h0.z, acc[2]);
        acc[3] = fmaf(cij, h0.w, acc[3]);
        acc[4] = fmaf(cij, h1.x, acc[4]);
        acc[5] = fmaf(cij, h1.y, acc[5]);
        acc[6] = fmaf(cij, h1.z, acc[6]);
        acc[7] = fmaf(cij, h1.w, acc[7]);
        acc[8] = fmaf(cij, h2.x, acc[8]);
        acc[9] = fmaf(cij, h2.y, acc[9]);
        acc[10] = fmaf(cij, h2.z, acc[10]);
        acc[11] = fmaf(cij, h2.w, acc[11]);
        acc[12] = fmaf(cij, h3.x, acc[12]);
        acc[13] = fmaf(cij, h3.y, acc[13]);
        acc[14] = fmaf(cij, h3.z, acc[14]);
        acc[15] = fmaf(cij, h3.w, acc[15]);
    }

    // Deterministic block reduction over ii
    if (MODE != 0) __syncthreads();  // ops smem reuse barrier not needed (red distinct), but spart ordering safe
#pragma unroll
    for (int m = 0; m < 16; m += 4) {
        *(float4*)&red[ii * JM + j * 16 + m] =
            make_float4(acc[m], acc[m + 1], acc[m + 2], acc[m + 3]);
    }
    __syncthreads();
    float v = 0.f;
#pragma unroll
    for (int k = 0; k < 16; k++) v += red[k * JM + t];
    const int WSLOT = (MODE == 1) ? 1 : 0;
    g_spart[WSLOT][(b * NCHUNK + chunk) * JM + t] = v;
}

// ---------------------------------------------------------------------------
// Final squash over all b: reduce g_spart[0] + squash -> d_out
// ---------------------------------------------------------------------------
__global__ void __launch_bounds__(256) squash_final(float* __restrict__ out) {
    const int b = blockIdx.x;
    const int t = threadIdx.x;
    float s = 0.f;
    const float* sp = g_spart[0] + b * (NCHUNK * JM) + t;
#pragma unroll
    for (int ch = 0; ch < NCHUNK; ch++) s += sp[ch * JM];
    float n2 = s * s;
#pragma unroll
    for (int o = 8; o >= 1; o >>= 1)
        n2 += __shfl_xor_sync(0xffffffffu, n2, o);
    const float scale = (n2 / (1.f + n2)) * rsqrtf(n2 + SQ_EPS);
    out[b * JM + t] = scale * s;
}

// ---------------------------------------------------------------------------
extern "C" void kernel_launch(void* const* d_in, const int* in_sizes, int n_in,
                              void* d_out, int out_size) {
    const float* x = (const float*)d_in[0];  // [B, I, N]
    const float* W = (const float*)d_in[1];  // [I, J, N, M]
    if (n_in >= 2 && in_sizes[0] > in_sizes[1]) {  // defensive order check
        const float* tmp = x; x = W; W = tmp;
    }
    float* out = (float*)d_out;

    // Batch-tiled schedule: per 32-b group, hat slice (67 MB) stays in L2
    // across the three routing passes.
    for (int g = 0; g < BB / GROUPB; g++) {
        const int b0 = g * GROUPB;
        dim3 pg(NCHUNK, GROUPB);
        hat_kernel<<<II, 256>>>(x, W, b0);
        pass_kernel<0><<<pg, 256>>>(b0);   // writes spart[0]
        pass_kernel<1><<<pg, 256>>>(b0);   // squash(spart[0]) -> op; writes spart[1], blog
        pass_kernel<2><<<pg, 256>>>(b0);   // squash(spart[1]) -> op; writes spart[0]
    }
    squash_final<<<BB, 256>>>(out);
}